// round 12
// baseline (speedup 1.0000x reference)
#include <cuda_runtime.h>
#include <math_constants.h>
#include <cstdint>

// Problem: B=4, T=4096, C=1024, H=64. Causal single-head attention.
// out = softmax(mask(scale * (x@Wq)(x@Wk)^T)) @ (x@Wv)

#define B_  4
#define T_  4096
#define C_  1024
#define H_  64
#define SCALE 0.125f   // 64^-0.5, folded into Wq during prep (exact pow2)

// tf32 hi/lo split storage (written by proj, read by attn)
__device__ __align__(16) float2 g_qhl[B_ * T_ * H_];   // [b*T+t][h] (q pre-scaled)
__device__ __align__(16) float2 g_khl[B_ * T_ * H_];   // [b*T+t][h]
__device__ __align__(16) float2 g_vT [B_ * H_ * T_];   // [b][h][t]  (transposed)
__device__ __align__(16) float2 g_wt [3 * H_ * C_];    // [p][n][k], 0=q(scaled),1=k,2=v

// ---------------------------------------------------------------------------
// helpers
// ---------------------------------------------------------------------------
__device__ __forceinline__ uint32_t cvt_tf32(float x) {
    uint32_t r;
    asm("cvt.rna.tf32.f32 %0, %1;" : "=r"(r) : "f"(x));
    return r;
}
__device__ __forceinline__ float2 split2(float x) {
    uint32_t hi = cvt_tf32(x);
    float fhi = __uint_as_float(hi);
    uint32_t lo = cvt_tf32(x - fhi);
    return make_float2(fhi, __uint_as_float(lo));
}
__device__ __forceinline__ void mma8(float c[4], const uint32_t a[4],
                                     uint32_t b0, uint32_t b1) {
    asm volatile(
        "mma.sync.aligned.m16n8k8.row.col.f32.tf32.tf32.f32 "
        "{%0,%1,%2,%3}, {%4,%5,%6,%7}, {%8,%9}, {%0,%1,%2,%3};\n"
        : "+f"(c[0]), "+f"(c[1]), "+f"(c[2]), "+f"(c[3])
        : "r"(a[0]), "r"(a[1]), "r"(a[2]), "r"(a[3]), "r"(b0), "r"(b1));
}
__device__ __forceinline__ uint32_t sptr(const void* p) {
    return (uint32_t)__cvta_generic_to_shared(p);
}
__device__ __forceinline__ void cp16(uint32_t s, const void* g) {
    asm volatile("cp.async.cg.shared.global [%0], [%1], 16;" :: "r"(s), "l"(g));
}
#define CP_COMMIT() asm volatile("cp.async.commit_group;")
#define CP_WAIT0()  asm volatile("cp.async.wait_group 0;" ::: "memory")

// ---------------------------------------------------------------------------
// prep: split W into tf32 hi/lo, transposed [n][k]; fold SCALE into Wq.
// ---------------------------------------------------------------------------
__global__ void prep_w(const float* __restrict__ Wq,
                       const float* __restrict__ Wk,
                       const float* __restrict__ Wv)
{
    int idx = blockIdx.x * 256 + threadIdx.x;     // 0..196607
    int p = idx >> 16;
    int r = idx & 65535;
    int k = r >> 6;
    int n = r & 63;
    const float* W = (p == 0) ? Wq : (p == 1 ? Wk : Wv);
    float v = W[k * 64 + n];
    if (p == 0) v *= SCALE;
    g_wt[p * 65536 + n * 1024 + k] = split2(v);
}

// ---------------------------------------------------------------------------
// Projection, 3xTF32 tensor cores, fused q/k/v. (unchanged from R10 — passed)
// ---------------------------------------------------------------------------
#define PW 34   // float2 row stride for 32-k chunks

__global__ __launch_bounds__(256)
void proj_kernel(const float* __restrict__ x)
{
    extern __shared__ float2 psm[];
    float2* xs0 = psm;                  // [128][34]
    float2* xs1 = xs0 + 128 * PW;
    float2* ws0 = xs1 + 128 * PW;       // [192][34]
    float2* ws1 = ws0 + 192 * PW;

    const int tid  = threadIdx.x;
    const int wid  = tid >> 5;
    const int lane = tid & 31;
    const int g    = lane >> 2;
    const int tig  = lane & 3;
    const int m0   = blockIdx.x * 128;
    const int rlo  = wid * 16 + g;
    const int rhi  = rlo + 8;

    float c[24][4];
#pragma unroll
    for (int f = 0; f < 24; f++)
#pragma unroll
        for (int j = 0; j < 4; j++) c[f][j] = 0.f;

    const int xrow = tid >> 1, xhalf = tid & 1;
    const float* xptr = x + (size_t)(m0 + xrow) * C_ + xhalf * 16;

    float4 xpre[4];
#pragma unroll
    for (int j = 0; j < 4; j++) xpre[j] = *(const float4*)(xptr + j * 4);

#pragma unroll
    for (int i = 0; i < 12; i++) {
        int idx = tid + i * 256;
        int n = idx >> 4, kp = idx & 15;
        cp16(sptr(ws0 + n * PW + kp * 2), g_wt + (size_t)n * 1024 + kp * 2);
    }
    CP_COMMIT();

#pragma unroll
    for (int j = 0; j < 4; j++) {
        float2 e0 = split2(xpre[j].x);
        float2 e1 = split2(xpre[j].y);
        float2 e2 = split2(xpre[j].z);
        float2 e3 = split2(xpre[j].w);
        float4* d = (float4*)(xs0 + xrow * PW + xhalf * 16 + j * 4);
        d[0] = make_float4(e0.x, e0.y, e1.x, e1.y);
        d[1] = make_float4(e2.x, e2.y, e3.x, e3.y);
    }
#pragma unroll
    for (int j = 0; j < 4; j++) xpre[j] = *(const float4*)(xptr + 32 + j * 4);

    for (int kc = 0; kc < 32; kc++) {
        const float2* xs = (kc & 1) ? xs1 : xs0;
        const float2* ws = (kc & 1) ? ws1 : ws0;
        CP_WAIT0();
        __syncthreads();

        if (kc + 1 < 32) {
            float2* wsn = (kc & 1) ? ws0 : ws1;
#pragma unroll
            for (int i = 0; i < 12; i++) {
                int idx = tid + i * 256;
                int n = idx >> 4, kp = idx & 15;
                cp16(sptr(wsn + n * PW + kp * 2),
                     g_wt + (size_t)n * 1024 + (kc + 1) * 32 + kp * 2);
            }
            CP_COMMIT();
            float2* xsn = (kc & 1) ? xs0 : xs1;
#pragma unroll
            for (int j = 0; j < 4; j++) {
                float2 e0 = split2(xpre[j].x);
                float2 e1 = split2(xpre[j].y);
                float2 e2 = split2(xpre[j].z);
                float2 e3 = split2(xpre[j].w);
                float4* d = (float4*)(xsn + xrow * PW + xhalf * 16 + j * 4);
                d[0] = make_float4(e0.x, e0.y, e1.x, e1.y);
                d[1] = make_float4(e2.x, e2.y, e3.x, e3.y);
            }
            if (kc + 2 < 32) {
                const float* xn = xptr + (kc + 2) * 32;
#pragma unroll
                for (int j = 0; j < 4; j++) xpre[j] = *(const float4*)(xn + j * 4);
            }
        }

#pragma unroll
        for (int k0 = 0; k0 < 32; k0 += 8) {
            uint32_t ahi[4], alo[4];
            {
                uint2 t;
                t = *(const uint2*)&xs[rlo * PW + k0 + tig];     ahi[0] = t.x; alo[0] = t.y;
                t = *(const uint2*)&xs[rhi * PW + k0 + tig];     ahi[1] = t.x; alo[1] = t.y;
                t = *(const uint2*)&xs[rlo * PW + k0 + tig + 4]; ahi[2] = t.x; alo[2] = t.y;
                t = *(const uint2*)&xs[rhi * PW + k0 + tig + 4]; ahi[3] = t.x; alo[3] = t.y;
            }
#pragma unroll
            for (int f = 0; f < 24; f++) {
                uint2 b0 = *(const uint2*)&ws[(f * 8 + g) * PW + k0 + tig];
                uint2 b1 = *(const uint2*)&ws[(f * 8 + g) * PW + k0 + tig + 4];
                mma8(c[f], ahi, b0.x, b1.x);
                mma8(c[f], ahi, b0.y, b1.y);
                mma8(c[f], alo, b0.x, b1.x);
            }
        }
    }

#pragma unroll
    for (int f = 0; f < 24; f++) {
        int p  = f >> 3;
        int hh = (f & 7) * 8 + tig * 2;
        float2 e0 = split2(c[f][0]);
        float2 e1 = split2(c[f][1]);
        float2 e2 = split2(c[f][2]);
        float2 e3 = split2(c[f][3]);
        if (p < 2) {
            float2* basep = (p == 0) ? g_qhl : g_khl;
            *(float4*)(basep + (size_t)(m0 + rlo) * 64 + hh) =
                make_float4(e0.x, e0.y, e1.x, e1.y);
            *(float4*)(basep + (size_t)(m0 + rhi) * 64 + hh) =
                make_float4(e2.x, e2.y, e3.x, e3.y);
        } else {
            int r0g = m0 + rlo, bb0 = r0g >> 12, t0 = r0g & 4095;
            int r1g = m0 + rhi, bb1 = r1g >> 12, t1 = r1g & 4095;
            g_vT[(size_t)bb0 * 262144 + (size_t)hh * 4096 + t0]       = e0;
            g_vT[(size_t)bb0 * 262144 + (size_t)(hh + 1) * 4096 + t0] = e1;
            g_vT[(size_t)bb1 * 262144 + (size_t)hh * 4096 + t1]       = e2;
            g_vT[(size_t)bb1 * 262144 + (size_t)(hh + 1) * 4096 + t1] = e3;
        }
    }
}

// ---------------------------------------------------------------------------
// Flash attention (causal), n-half split-K + SOFTWARE-PIPELINED S.
// 256 thr = 8 warps; warp (rg, nh) owns rows rg*16..+15 x keys nh*32..+31,
// private online softmax (m,l,O), register-resident P via quad permute,
// combined once per side (R10 scheme, unchanged math).
// S for tile jt+1 is issued into a second register set BEFORE softmax/PV of
// tile jt, so the tensor pipe executes S_{jt+1} while the ALU/MUFU softmax
// chain of tile jt runs. K double-buffered, V TRIPLE-buffered (V_jt is read
// the same iteration V_{jt+2} prefetch lands). One __syncthreads per tile.
// Pair schedule (i, 63-i): 65 tiles per block. Grid (32, B).
// ---------------------------------------------------------------------------
#define AS 68    // float2 row stride (2*AS mod 32 == 8 -> conflict-free frags)
#define OST 72   // float stride for combine overlay

__device__ __forceinline__ void issue_k(const float2* kb, int jt, float2* Ks, int tid)
{
#pragma unroll
    for (int i = 0; i < 8; i++) {
        int c = tid + i * 256;
        int r = c >> 5, q = c & 31;
        cp16(sptr(Ks + r * AS + q * 2), kb + (size_t)(jt * 64 + r) * 64 + q * 2);
    }
}
__device__ __forceinline__ void issue_v(const float2* vb, int jt, float2* Vt, int tid)
{
#pragma unroll
    for (int i = 0; i < 8; i++) {
        int c = tid + i * 256;
        int r = c >> 5, q = c & 31;
        cp16(sptr(Vt + r * AS + q * 2), vb + (size_t)r * 4096 + jt * 64 + q * 2);
    }
}

// Issue S = Q.K^T (3xTF32) for this warp's m16 x n32 key-half into s.
__device__ __forceinline__ void sgemm_issue(const float2* Kst, int kB, int g, int tig,
                                            const uint32_t qhi[8][4],
                                            const uint32_t qlo[8][4],
                                            float s[4][4])
{
#pragma unroll
    for (int f = 0; f < 4; f++)
#pragma unroll
        for (int j = 0; j < 4; j++) s[f][j] = 0.f;
#pragma unroll
    for (int i = 0; i < 8; i++) {
#pragma unroll
        for (int f = 0; f < 4; f++) {
            uint2 u0 = *(const uint2*)&Kst[(kB + 8 * f + g) * AS + 8 * i + tig];
            uint2 u1 = *(const uint2*)&Kst[(kB + 8 * f + g) * AS + 8 * i + tig + 4];
            mma8(s[f], qhi[i], u0.x, u1.x);
            mma8(s[f], qhi[i], u0.y, u1.y);
            mma8(s[f], qlo[i], u0.x, u1.x);
        }
    }
}

__global__ __launch_bounds__(256)
void attn_kernel(float* __restrict__ out)
{
    extern __shared__ float2 smp[];
    float2* K0 = smp;
    float2* K1 = K0 + 64 * AS;
    float2* V0 = K1 + 64 * AS;
    float2* V1 = V0 + 64 * AS;
    float2* V2 = V1 + 64 * AS;
    float*  Osm = (float*)K0;             // combine overlay: [64][OST]
    float*  msm = (float*)K1;             // [64]
    float*  lsm = msm + 64;               // [64]

    const int b    = blockIdx.y;
    const int pair = blockIdx.x;
    const int tid  = threadIdx.x;
    const int wid  = tid >> 5;
    const int lane = tid & 31;
    const int g    = lane >> 2;
    const int tig  = lane & 3;
    const int rg   = wid & 3;
    const int nh   = wid >> 2;            // key half: 0 or 1
    const int kB   = nh * 32;
    const int rlo  = rg * 16 + g;
    const int rhi  = rlo + 8;
    const int src0 = (lane & 28) | (tig >> 1);
    const int src1 = src0 + 2;

    const float2* kb = g_khl + (size_t)b * T_ * 64;
    const float2* vb = g_vT  + (size_t)b * 64 * T_;
    const float2* qb = g_qhl + (size_t)b * T_ * 64;

    for (int side = 0; side < 2; side++) {
        const int qt = side ? (63 - pair) : pair;
        const int q0 = qt * 64;
        const int ntile = qt + 1;

        __syncthreads();   // prior side's smem consumers (incl. combine) done

        // Q fragments straight from gmem
        uint32_t qhi[8][4], qlo[8][4];
        {
            const uint2* qr0 = (const uint2*)(qb + (size_t)(q0 + rlo) * 64);
            const uint2* qr1 = (const uint2*)(qb + (size_t)(q0 + rhi) * 64);
#pragma unroll
            for (int i = 0; i < 8; i++) {
                uint2 t;
                t = qr0[8 * i + tig];     qhi[i][0] = t.x; qlo[i][0] = t.y;
                t = qr1[8 * i + tig];     qhi[i][1] = t.x; qlo[i][1] = t.y;
                t = qr0[8 * i + tig + 4]; qhi[i][2] = t.x; qlo[i][2] = t.y;
                t = qr1[8 * i + tig + 4]; qhi[i][3] = t.x; qlo[i][3] = t.y;
            }
        }

        // prologue: KV tile 0; then S_0 while KV tile 1 loads
        issue_k(kb, 0, K0, tid);
        issue_v(vb, 0, V0, tid);
        CP_COMMIT();
        CP_WAIT0();
        __syncthreads();
        if (ntile > 1) {
            issue_k(kb, 1, K1, tid);
            issue_v(vb, 1, V1, tid);
            CP_COMMIT();
        }

        float sA[4][4], sB[4][4];
        sgemm_issue(K0, kB, g, tig, qhi, qlo, sA);

        float mA = -CUDART_INF_F, mB = -CUDART_INF_F;
        float lA = 0.f, lB = 0.f;
        float o[8][4];
#pragma unroll
        for (int f = 0; f < 8; f++)
#pragma unroll
            for (int j = 0; j < 4; j++) o[f][j] = 0.f;

        int vcur = 0;   // jt % 3
        for (int jt = 0; jt < ntile; jt++) {
            const int nx = jt + 1;
            if (nx < ntile) {
                CP_WAIT0();
                __syncthreads();   // K/V tile nx resident; K[jt&1], V[(jt+2)%3] free
                if (nx + 1 < ntile) {
                    float2* kn = ((nx + 1) & 1) ? K1 : K0;
                    int vn = vcur + 2; if (vn >= 3) vn -= 3;
                    float2* vnp = (vn == 0) ? V0 : (vn == 1) ? V1 : V2;
                    issue_k(kb, nx + 1, kn, tid);
                    issue_v(vb, nx + 1, vnp, tid);
                    CP_COMMIT();
                }
                // issue next tile's S NOW -> tensor pipe busy during softmax
                sgemm_issue((nx & 1) ? K1 : K0, kB, g, tig, qhi, qlo, sB);
            }

            // ---- causal mask (diagonal tile only)
            if (jt == ntile - 1) {
                const int rglo = q0 + rlo, rghi = q0 + rhi;
                const int cb = jt * 64 + kB;
#pragma unroll
                for (int f = 0; f < 4; f++) {
                    int c0 = cb + 8 * f + 2 * tig;
                    if (c0 > rglo)     sA[f][0] = -1e30f;
                    if (c0 + 1 > rglo) sA[f][1] = -1e30f;
                    if (c0 > rghi)     sA[f][2] = -1e30f;
                    if (c0 + 1 > rghi) sA[f][3] = -1e30f;
                }
            }

            // ---- warp-local row max over this key half
            float pmA = -CUDART_INF_F, pmB = -CUDART_INF_F;
#pragma unroll
            for (int f = 0; f < 4; f++) {
                pmA = fmaxf(pmA, fmaxf(sA[f][0], sA[f][1]));
                pmB = fmaxf(pmB, fmaxf(sA[f][2], sA[f][3]));
            }
            pmA = fmaxf(pmA, __shfl_xor_sync(0xffffffffu, pmA, 1));
            pmA = fmaxf(pmA, __shfl_xor_sync(0xffffffffu, pmA, 2));
            pmB = fmaxf(pmB, __shfl_xor_sync(0xffffffffu, pmB, 1));
            pmB = fmaxf(pmB, __shfl_xor_sync(0xffffffffu, pmB, 2));

            const float mnA = fmaxf(mA, pmA);
            const float mnB = fmaxf(mB, pmB);
            const float aA  = __expf(mA - mnA);
            const float aB  = __expf(mB - mnB);
            mA = mnA; mB = mnB;

            // ---- p = exp(s - m), partial l, rescale O
            float psA = 0.f, psB = 0.f;
#pragma unroll
            for (int f = 0; f < 4; f++) {
                sA[f][0] = __expf(sA[f][0] - mnA);
                sA[f][1] = __expf(sA[f][1] - mnA);
                sA[f][2] = __expf(sA[f][2] - mnB);
                sA[f][3] = __expf(sA[f][3] - mnB);
                psA += sA[f][0] + sA[f][1];
                psB += sA[f][2] + sA[f][3];
            }
            psA += __shfl_xor_sync(0xffffffffu, psA, 1);
            psA += __shfl_xor_sync(0xffffffffu, psA, 2);
            psB += __shfl_xor_sync(0xffffffffu, psB, 1);
            psB += __shfl_xor_sync(0xffffffffu, psB, 2);
            lA = lA * aA + psA;
            lB = lB * aB + psB;
#pragma unroll
            for (int f = 0; f < 8; f++) {
                o[f][0] *= aA; o[f][1] *= aA;
                o[f][2] *= aB; o[f][3] *= aB;
            }

            // ---- O += P.V (2-term), P permuted C->A via quad shuffles
            const float2* Vtt = (vcur == 0) ? V0 : (vcur == 1) ? V1 : V2;
#pragma unroll
            for (int f = 0; f < 4; f++) {
                uint32_t u0 = cvt_tf32(sA[f][0]);
                uint32_t u1 = cvt_tf32(sA[f][1]);
                uint32_t u2 = cvt_tf32(sA[f][2]);
                uint32_t u3 = cvt_tf32(sA[f][3]);
                uint32_t pa[4];
                {
                    uint32_t x0 = __shfl_sync(0xffffffffu, u0, src0);
                    uint32_t x1 = __shfl_sync(0xffffffffu, u1, src0);
                    pa[0] = (tig & 1) ? x1 : x0;
                    uint32_t y0 = __shfl_sync(0xffffffffu, u2, src0);
                    uint32_t y1 = __shfl_sync(0xffffffffu, u3, src0);
                    pa[1] = (tig & 1) ? y1 : y0;
                    uint32_t z0 = __shfl_sync(0xffffffffu, u0, src1);
                    uint32_t z1 = __shfl_sync(0xffffffffu, u1, src1);
                    pa[2] = (tig & 1) ? z1 : z0;
                    uint32_t w0 = __shfl_sync(0xffffffffu, u2, src1);
                    uint32_t w1 = __shfl_sync(0xffffffffu, u3, src1);
                    pa[3] = (tig & 1) ? w1 : w0;
                }
#pragma unroll
                for (int fo = 0; fo < 8; fo++) {
                    uint2 v0 = *(const uint2*)&Vtt[(8 * fo + g) * AS + kB + 8 * f + tig];
                    uint2 v1 = *(const uint2*)&Vtt[(8 * fo + g) * AS + kB + 8 * f + tig + 4];
                    mma8(o[fo], pa, v0.x, v1.x);
                    mma8(o[fo], pa, v0.y, v1.y);
                }
            }

            if (nx < ntile) {
#pragma unroll
                for (int f = 0; f < 4; f++)
#pragma unroll
                    for (int j = 0; j < 4; j++) sA[f][j] = sB[f][j];
            }
            vcur++; if (vcur == 3) vcur = 0;
        }

        // ---- combine the two key-half groups, write output
        __syncthreads();   // all K/V reads done; safe to overlay K0/K1
        if (nh == 1) {
#pragma unroll
            for (int f = 0; f < 8; f++) {
                int cc = 8 * f + 2 * tig;
                *(float2*)&Osm[rlo * OST + cc] = make_float2(o[f][0], o[f][1]);
                *(float2*)&Osm[rhi * OST + cc] = make_float2(o[f][2], o[f][3]);
            }
            if (tig == 0) {
                msm[rlo] = mA; lsm[rlo] = lA;
                msm[rhi] = mB; lsm[rhi] = lB;
            }
        }
        __syncthreads();
        if (nh == 0) {
            const float m1A = msm[rlo], l1A = lsm[rlo];
            const float m1B = msm[rhi], l1B = lsm[rhi];
            const float MA = fmaxf(mA, m1A), MB = fmaxf(mB, m1B);
            const float w0A = __expf(mA - MA),  w1A = __expf(m1A - MA);
            const float w0B = __expf(mB - MB),  w1B = __expf(m1B - MB);
            const float invA = 1.f / (lA * w0A + l1A * w1A);
            const float invB = 1.f / (lB * w0B + l1B * w1B);
            float* or0 = out + ((size_t)b * T_ + q0 + rlo) * H_;
            float* or1 = out + ((size_t)b * T_ + q0 + rhi) * H_;
#pragma unroll
            for (int f = 0; f < 8; f++) {
                int cc = 8 * f + 2 * tig;
                float2 p0 = *(const float2*)&Osm[rlo * OST + cc];
                float2 p1 = *(const float2*)&Osm[rhi * OST + cc];
                *(float2*)&or0[cc] = make_float2(
                    (o[f][0] * w0A + p0.x * w1A) * invA,
                    (o[f][1] * w0A + p0.y * w1A) * invA);
                *(float2*)&or1[cc] = make_float2(
                    (o[f][2] * w0B + p1.x * w1B) * invB,
                    (o[f][3] * w0B + p1.y * w1B) * invB);
            }
        }
    }
}

// ---------------------------------------------------------------------------

extern "C" void kernel_launch(void* const* d_in, const int* in_sizes, int n_in,
                              void* d_out, int out_size)
{
    const float* x  = (const float*)d_in[0];
    const float* Wk = (const float*)d_in[1];
    const float* Wq = (const float*)d_in[2];
    const float* Wv = (const float*)d_in[3];
    float* out = (float*)d_out;

    prep_w<<<768, 256>>>(Wq, Wk, Wv);

    const int psmem = (2 * 128 * PW + 2 * 192 * PW) * (int)sizeof(float2); // 174080
    cudaFuncSetAttribute(proj_kernel, cudaFuncAttributeMaxDynamicSharedMemorySize, psmem);
    proj_kernel<<<128, 256, psmem>>>(x);

    const int asmem = 5 * 64 * AS * (int)sizeof(float2); // 174080 (2K + 3V)
    cudaFuncSetAttribute(attn_kernel, cudaFuncAttributeMaxDynamicSharedMemorySize, asmem);
    attn_kernel<<<dim3(32, B_), 256, asmem>>>(out);
}

// round 13
// speedup vs baseline: 1.2730x; 1.2730x over previous
#include <cuda_runtime.h>
#include <math_constants.h>
#include <cstdint>

// Problem: B=4, T=4096, C=1024, H=64. Causal single-head attention.
// out = softmax(mask(scale * (x@Wq)(x@Wk)^T)) @ (x@Wv)

#define B_  4
#define T_  4096
#define C_  1024
#define H_  64
#define SCALE 0.125f   // 64^-0.5, folded into Wq during prep (exact pow2)

// bf16 hi/lo packed storage (written by proj epilogue, read by attn).
// Word format: uint2{ bf16x2(hi(e0),hi(e1)), bf16x2(lo(e0),lo(e1)) } for two
// adjacent elements e0,e1 along the packing dimension.
__device__ __align__(16) uint2 g_q[B_ * T_ * 32];       // [t][hpair], q pre-scaled
__device__ __align__(16) uint2 g_k[B_ * T_ * 32];       // [t][hpair]
__device__ __align__(16) uint2 g_v[B_ * 64 * 2048];     // [b][h][tpair] (transposed)
__device__ __align__(16) float2 g_wt[3 * H_ * C_];      // tf32 hi/lo for proj (prep)

// ---------------------------------------------------------------------------
// helpers
// ---------------------------------------------------------------------------
__device__ __forceinline__ uint32_t cvt_tf32(float x) {
    uint32_t r;
    asm("cvt.rna.tf32.f32 %0, %1;" : "=r"(r) : "f"(x));
    return r;
}
__device__ __forceinline__ float2 split2(float x) {
    uint32_t hi = cvt_tf32(x);
    float fhi = __uint_as_float(hi);
    uint32_t lo = cvt_tf32(x - fhi);
    return make_float2(fhi, __uint_as_float(lo));
}
// tf32 k8 mma (proj)
__device__ __forceinline__ void mma8(float c[4], const uint32_t a[4],
                                     uint32_t b0, uint32_t b1) {
    asm volatile(
        "mma.sync.aligned.m16n8k8.row.col.f32.tf32.tf32.f32 "
        "{%0,%1,%2,%3}, {%4,%5,%6,%7}, {%8,%9}, {%0,%1,%2,%3};\n"
        : "+f"(c[0]), "+f"(c[1]), "+f"(c[2]), "+f"(c[3])
        : "r"(a[0]), "r"(a[1]), "r"(a[2]), "r"(a[3]), "r"(b0), "r"(b1));
}
// bf16 k16 mma (attn)
__device__ __forceinline__ void mma16(float c[4], const uint32_t a[4],
                                      uint32_t b0, uint32_t b1) {
    asm volatile(
        "mma.sync.aligned.m16n8k16.row.col.f32.bf16.bf16.f32 "
        "{%0,%1,%2,%3}, {%4,%5,%6,%7}, {%8,%9}, {%0,%1,%2,%3};\n"
        : "+f"(c[0]), "+f"(c[1]), "+f"(c[2]), "+f"(c[3])
        : "r"(a[0]), "r"(a[1]), "r"(a[2]), "r"(a[3]), "r"(b0), "r"(b1));
}
// pack: upper = up, lower = lo
__device__ __forceinline__ uint32_t bfpack(float up, float lo) {
    uint32_t r;
    asm("cvt.rn.bf16x2.f32 %0, %1, %2;" : "=r"(r) : "f"(up), "f"(lo));
    return r;
}
__device__ __forceinline__ float bflo_f(uint32_t p) { return __uint_as_float(p << 16); }
__device__ __forceinline__ float bfhi_f(uint32_t p) { return __uint_as_float(p & 0xffff0000u); }

__device__ __forceinline__ uint32_t sptr(const void* p) {
    return (uint32_t)__cvta_generic_to_shared(p);
}
__device__ __forceinline__ void cp16(uint32_t s, const void* g) {
    asm volatile("cp.async.cg.shared.global [%0], [%1], 16;" :: "r"(s), "l"(g));
}
#define CP_COMMIT() asm volatile("cp.async.commit_group;")
#define CP_WAIT0()  asm volatile("cp.async.wait_group 0;" ::: "memory")

// ---------------------------------------------------------------------------
// prep: split W into tf32 hi/lo, transposed [n][k]; fold SCALE into Wq.
// ---------------------------------------------------------------------------
__global__ void prep_w(const float* __restrict__ Wq,
                       const float* __restrict__ Wk,
                       const float* __restrict__ Wv)
{
    int idx = blockIdx.x * 256 + threadIdx.x;
    int p = idx >> 16;
    int r = idx & 65535;
    int k = r >> 6;
    int n = r & 63;
    const float* W = (p == 0) ? Wq : (p == 1 ? Wk : Wv);
    float v = W[k * 64 + n];
    if (p == 0) v *= SCALE;
    g_wt[p * 65536 + n * 1024 + k] = split2(v);
}

// ---------------------------------------------------------------------------
// Projection, 3xTF32 tensor cores (compute unchanged from R10 — known good).
// NEW EPILOGUE: emit bf16 hi/lo packed words (q/k by h-pair; v transposed by
// t-pair via 4-shfl row pairing).
// ---------------------------------------------------------------------------
#define PW 34

__global__ __launch_bounds__(256)
void proj_kernel(const float* __restrict__ x)
{
    extern __shared__ float2 psm[];
    float2* xs0 = psm;
    float2* xs1 = xs0 + 128 * PW;
    float2* ws0 = xs1 + 128 * PW;
    float2* ws1 = ws0 + 192 * PW;

    const int tid  = threadIdx.x;
    const int wid  = tid >> 5;
    const int lane = tid & 31;
    const int g    = lane >> 2;
    const int tig  = lane & 3;
    const int m0   = blockIdx.x * 128;
    const int rlo  = wid * 16 + g;
    const int rhi  = rlo + 8;

    float c[24][4];
#pragma unroll
    for (int f = 0; f < 24; f++)
#pragma unroll
        for (int j = 0; j < 4; j++) c[f][j] = 0.f;

    const int xrow = tid >> 1, xhalf = tid & 1;
    const float* xptr = x + (size_t)(m0 + xrow) * C_ + xhalf * 16;

    float4 xpre[4];
#pragma unroll
    for (int j = 0; j < 4; j++) xpre[j] = *(const float4*)(xptr + j * 4);

#pragma unroll
    for (int i = 0; i < 12; i++) {
        int idx = tid + i * 256;
        int n = idx >> 4, kp = idx & 15;
        cp16(sptr(ws0 + n * PW + kp * 2), g_wt + (size_t)n * 1024 + kp * 2);
    }
    CP_COMMIT();

#pragma unroll
    for (int j = 0; j < 4; j++) {
        float2 e0 = split2(xpre[j].x);
        float2 e1 = split2(xpre[j].y);
        float2 e2 = split2(xpre[j].z);
        float2 e3 = split2(xpre[j].w);
        float4* d = (float4*)(xs0 + xrow * PW + xhalf * 16 + j * 4);
        d[0] = make_float4(e0.x, e0.y, e1.x, e1.y);
        d[1] = make_float4(e2.x, e2.y, e3.x, e3.y);
    }
#pragma unroll
    for (int j = 0; j < 4; j++) xpre[j] = *(const float4*)(xptr + 32 + j * 4);

    for (int kc = 0; kc < 32; kc++) {
        const float2* xs = (kc & 1) ? xs1 : xs0;
        const float2* ws = (kc & 1) ? ws1 : ws0;
        CP_WAIT0();
        __syncthreads();

        if (kc + 1 < 32) {
            float2* wsn = (kc & 1) ? ws0 : ws1;
#pragma unroll
            for (int i = 0; i < 12; i++) {
                int idx = tid + i * 256;
                int n = idx >> 4, kp = idx & 15;
                cp16(sptr(wsn + n * PW + kp * 2),
                     g_wt + (size_t)n * 1024 + (kc + 1) * 32 + kp * 2);
            }
            CP_COMMIT();
            float2* xsn = (kc & 1) ? xs0 : xs1;
#pragma unroll
            for (int j = 0; j < 4; j++) {
                float2 e0 = split2(xpre[j].x);
                float2 e1 = split2(xpre[j].y);
                float2 e2 = split2(xpre[j].z);
                float2 e3 = split2(xpre[j].w);
                float4* d = (float4*)(xsn + xrow * PW + xhalf * 16 + j * 4);
                d[0] = make_float4(e0.x, e0.y, e1.x, e1.y);
                d[1] = make_float4(e2.x, e2.y, e3.x, e3.y);
            }
            if (kc + 2 < 32) {
                const float* xn = xptr + (kc + 2) * 32;
#pragma unroll
                for (int j = 0; j < 4; j++) xpre[j] = *(const float4*)(xn + j * 4);
            }
        }

#pragma unroll
        for (int k0 = 0; k0 < 32; k0 += 8) {
            uint32_t ahi[4], alo[4];
            {
                uint2 t;
                t = *(const uint2*)&xs[rlo * PW + k0 + tig];     ahi[0] = t.x; alo[0] = t.y;
                t = *(const uint2*)&xs[rhi * PW + k0 + tig];     ahi[1] = t.x; alo[1] = t.y;
                t = *(const uint2*)&xs[rlo * PW + k0 + tig + 4]; ahi[2] = t.x; alo[2] = t.y;
                t = *(const uint2*)&xs[rhi * PW + k0 + tig + 4]; ahi[3] = t.x; alo[3] = t.y;
            }
#pragma unroll
            for (int f = 0; f < 24; f++) {
                uint2 b0 = *(const uint2*)&ws[(f * 8 + g) * PW + k0 + tig];
                uint2 b1 = *(const uint2*)&ws[(f * 8 + g) * PW + k0 + tig + 4];
                mma8(c[f], ahi, b0.x, b1.x);
                mma8(c[f], ahi, b0.y, b1.y);
                mma8(c[f], alo, b0.x, b1.x);
            }
        }
    }

    // ---- epilogue: bf16 hi/lo packed outputs ----
#pragma unroll
    for (int f = 0; f < 24; f++) {
        int p  = f >> 3;
        int hh = (f & 7) * 8 + tig * 2;          // h column base (even)
        float c0 = c[f][0], c1 = c[f][1], c2 = c[f][2], c3 = c[f][3];
        if (p < 2) {
            // q/k: word = two adjacent h (hh, hh+1) of one row
            uint2* basep = (p == 0) ? g_q : g_k;
            uint32_t h0 = bfpack(c1, c0);
            uint32_t l0 = bfpack(c1 - bfhi_f(h0), c0 - bflo_f(h0));
            basep[(size_t)(m0 + rlo) * 32 + (f & 7) * 4 + tig] = make_uint2(h0, l0);
            uint32_t h1 = bfpack(c3, c2);
            uint32_t l1 = bfpack(c3 - bfhi_f(h1), c2 - bflo_f(h1));
            basep[(size_t)(m0 + rhi) * 32 + (f & 7) * 4 + tig] = make_uint2(h1, l1);
        } else {
            // v transposed: word = two adjacent t (row, row+1) of one h.
            // row+1's value lives at lane+4 (g+1); even-g lanes store.
            float n0 = __shfl_down_sync(0xffffffffu, c0, 4);
            float n1 = __shfl_down_sync(0xffffffffu, c1, 4);
            float n2 = __shfl_down_sync(0xffffffffu, c2, 4);
            float n3 = __shfl_down_sync(0xffffffffu, c3, 4);
            if ((g & 1) == 0) {
                int t0g = m0 + rlo;             // even
                int t1g = m0 + rhi;             // even
                int bb0 = t0g >> 12, tt0 = t0g & 4095;
                int bb1 = t1g >> 12, tt1 = t1g & 4095;
                uint32_t h, l;
                h = bfpack(n0, c0);
                l = bfpack(n0 - bfhi_f(h), c0 - bflo_f(h));
                g_v[(size_t)bb0 * 131072 + (size_t)hh * 2048 + (tt0 >> 1)] = make_uint2(h, l);
                h = bfpack(n1, c1);
                l = bfpack(n1 - bfhi_f(h), c1 - bflo_f(h));
                g_v[(size_t)bb0 * 131072 + (size_t)(hh + 1) * 2048 + (tt0 >> 1)] = make_uint2(h, l);
                h = bfpack(n2, c2);
                l = bfpack(n2 - bfhi_f(h), c2 - bflo_f(h));
                g_v[(size_t)bb1 * 131072 + (size_t)hh * 2048 + (tt1 >> 1)] = make_uint2(h, l);
                h = bfpack(n3, c3);
                l = bfpack(n3 - bfhi_f(h), c3 - bflo_f(h));
                g_v[(size_t)bb1 * 131072 + (size_t)(hh + 1) * 2048 + (tt1 >> 1)] = make_uint2(h, l);
            }
        }
    }
}

// ---------------------------------------------------------------------------
// Flash attention (causal), bf16 m16n8k16 hi/lo 3-term, n-half split-K
// (R10 scheduling: KV double-buffer, 1 barrier/tile, per-side combine).
// 256 thr = 8 warps, warp (rg, nh): rows rg*16..+15 x keys nh*32..+31.
// S: 3-term (Qhi.Khi + Qlo.Khi + Qhi.Klo). PV: 3-term (Phi.Vhi + Plo.Vhi +
// Phi.Vlo) — with k16 the P C-frag IS the A-frag layout: zero shuffles.
// smem tiles: K[key][hpair] / V[h][tpair], uint2 words {hi-pair, lo-pair},
// row stride 36 words (72B-stride/8B word: 72 mod 32 = 8 -> conflict-free).
// Pair schedule (i, 63-i): 65 tiles per block. Grid (32, B).
// ---------------------------------------------------------------------------
#define KST 36   // uint2 row stride
#define OST 72   // float stride for combine overlay

__device__ __forceinline__ void issue_kv(const uint2* kb, const uint2* vb,
                                         int jt, uint2* Ks, uint2* Vt, int tid)
{
#pragma unroll
    for (int i = 0; i < 4; i++) {
        int c = tid + i * 256;            // 0..1023
        int r = c >> 4, q = (c & 15) * 2; // row, word offset (16B chunks)
        cp16(sptr(Ks + r * KST + q), kb + (size_t)(jt * 64 + r) * 32 + q);
        cp16(sptr(Vt + r * KST + q), vb + (size_t)r * 2048 + jt * 32 + q);
    }
}

__global__ __launch_bounds__(256)
void attn_kernel(float* __restrict__ out)
{
    extern __shared__ uint2 smp[];
    uint2* K0 = smp;
    uint2* K1 = K0 + 64 * KST;
    uint2* V0 = K1 + 64 * KST;
    uint2* V1 = V0 + 64 * KST;
    float* Osm = (float*)K0;              // combine overlay [64][OST] = 18432B
    float* msm = (float*)V0;              // [64]
    float* lsm = msm + 64;                // [64]

    const int b    = blockIdx.y;
    const int pair = blockIdx.x;
    const int tid  = threadIdx.x;
    const int wid  = tid >> 5;
    const int lane = tid & 31;
    const int g    = lane >> 2;
    const int tig  = lane & 3;
    const int rg   = wid & 3;
    const int nh   = wid >> 2;            // key half: 0 or 1
    const int kB   = nh * 32;
    const int rlo  = rg * 16 + g;
    const int rhi  = rlo + 8;

    const uint2* kb = g_k + (size_t)b * T_ * 32;
    const uint2* vb = g_v + (size_t)b * 131072;
    const uint2* qb = g_q + (size_t)b * T_ * 32;

    for (int side = 0; side < 2; side++) {
        const int qt = side ? (63 - pair) : pair;
        const int q0 = qt * 64;
        const int ntile = qt + 1;

        __syncthreads();   // prior side's smem consumers (incl. combine) done

        // Q fragments straight from gmem (bf16 hi/lo packed)
        uint32_t qhi[4][4], qlo[4][4];
        {
            const uint2* qr0 = qb + (size_t)(q0 + rlo) * 32;
            const uint2* qr1 = qb + (size_t)(q0 + rhi) * 32;
#pragma unroll
            for (int i = 0; i < 4; i++) {
                uint2 t;
                t = qr0[8 * i + tig];     qhi[i][0] = t.x; qlo[i][0] = t.y;
                t = qr1[8 * i + tig];     qhi[i][1] = t.x; qlo[i][1] = t.y;
                t = qr0[8 * i + tig + 4]; qhi[i][2] = t.x; qlo[i][2] = t.y;
                t = qr1[8 * i + tig + 4]; qhi[i][3] = t.x; qlo[i][3] = t.y;
            }
        }

        issue_kv(kb, vb, 0, K0, V0, tid);
        CP_COMMIT();

        float mA = -CUDART_INF_F, mB = -CUDART_INF_F;
        float lA = 0.f, lB = 0.f;
        float o[8][4];
#pragma unroll
        for (int f = 0; f < 8; f++)
#pragma unroll
            for (int j = 0; j < 4; j++) o[f][j] = 0.f;

        for (int jt = 0; jt < ntile; jt++) {
            CP_WAIT0();
            __syncthreads();   // KV[jt&1] visible; other buffer free

            const uint2* Kst = (jt & 1) ? K1 : K0;
            const uint2* Vtt = (jt & 1) ? V1 : V0;
            if (jt + 1 < ntile) {
                issue_kv(kb, vb, jt + 1, (jt & 1) ? K0 : K1,
                         (jt & 1) ? V0 : V1, tid);
                CP_COMMIT();
            }

            // ---- S = Q.K^T (bf16 3-term), warp tile m16 x n32
            float s[4][4];
#pragma unroll
            for (int f = 0; f < 4; f++)
#pragma unroll
                for (int j = 0; j < 4; j++) s[f][j] = 0.f;

#pragma unroll
            for (int i = 0; i < 4; i++) {
#pragma unroll
                for (int f = 0; f < 4; f++) {
                    int krow = (kB + 8 * f + g) * KST + 8 * i;
                    uint2 u0 = Kst[krow + tig];
                    uint2 u1 = Kst[krow + tig + 4];
                    mma16(s[f], qhi[i], u0.x, u1.x);
                    mma16(s[f], qlo[i], u0.x, u1.x);
                    mma16(s[f], qhi[i], u0.y, u1.y);
                }
            }

            // ---- causal mask (diagonal tile only)
            if (jt == ntile - 1) {
                const int rglo = q0 + rlo, rghi = q0 + rhi;
                const int cb = jt * 64 + kB;
#pragma unroll
                for (int f = 0; f < 4; f++) {
                    int c0 = cb + 8 * f + 2 * tig;
                    if (c0 > rglo)     s[f][0] = -1e30f;
                    if (c0 + 1 > rglo) s[f][1] = -1e30f;
                    if (c0 > rghi)     s[f][2] = -1e30f;
                    if (c0 + 1 > rghi) s[f][3] = -1e30f;
                }
            }

            // ---- warp-local row max (quad shuffle)
            float pmA = -CUDART_INF_F, pmB = -CUDART_INF_F;
#pragma unroll
            for (int f = 0; f < 4; f++) {
                pmA = fmaxf(pmA, fmaxf(s[f][0], s[f][1]));
                pmB = fmaxf(pmB, fmaxf(s[f][2], s[f][3]));
            }
            pmA = fmaxf(pmA, __shfl_xor_sync(0xffffffffu, pmA, 1));
            pmA = fmaxf(pmA, __shfl_xor_sync(0xffffffffu, pmA, 2));
            pmB = fmaxf(pmB, __shfl_xor_sync(0xffffffffu, pmB, 1));
            pmB = fmaxf(pmB, __shfl_xor_sync(0xffffffffu, pmB, 2));

            const float mnA = fmaxf(mA, pmA);
            const float mnB = fmaxf(mB, pmB);
            const float aA  = __expf(mA - mnA);
            const float aB  = __expf(mB - mnB);
            mA = mnA; mB = mnB;

            // ---- p = exp(s - m), partial l, rescale O
            float psA = 0.f, psB = 0.f;
#pragma unroll
            for (int f = 0; f < 4; f++) {
                s[f][0] = __expf(s[f][0] - mnA);
                s[f][1] = __expf(s[f][1] - mnA);
                s[f][2] = __expf(s[f][2] - mnB);
                s[f][3] = __expf(s[f][3] - mnB);
                psA += s[f][0] + s[f][1];
                psB += s[f][2] + s[f][3];
            }
            psA += __shfl_xor_sync(0xffffffffu, psA, 1);
            psA += __shfl_xor_sync(0xffffffffu, psA, 2);
            psB += __shfl_xor_sync(0xffffffffu, psB, 1);
            psB += __shfl_xor_sync(0xffffffffu, psB, 2);
            lA = lA * aA + psA;
            lB = lB * aB + psB;
#pragma unroll
            for (int f = 0; f < 8; f++) {
                o[f][0] *= aA; o[f][1] *= aA;
                o[f][2] *= aB; o[f][3] *= aB;
            }

            // ---- O += P.V (bf16 3-term). With k16 the C-frag IS the A-frag:
            //      no shuffles; just local bf16 packs (hi + residual lo).
#pragma unroll
            for (int j = 0; j < 2; j++) {
                uint32_t phi[4], plo[4];
                phi[0] = bfpack(s[2 * j][1], s[2 * j][0]);
                phi[1] = bfpack(s[2 * j][3], s[2 * j][2]);
                phi[2] = bfpack(s[2 * j + 1][1], s[2 * j + 1][0]);
                phi[3] = bfpack(s[2 * j + 1][3], s[2 * j + 1][2]);
                plo[0] = bfpack(s[2 * j][1] - bfhi_f(phi[0]),
                                s[2 * j][0] - bflo_f(phi[0]));
                plo[1] = bfpack(s[2 * j][3] - bfhi_f(phi[1]),
                                s[2 * j][2] - bflo_f(phi[1]));
                plo[2] = bfpack(s[2 * j + 1][1] - bfhi_f(phi[2]),
                                s[2 * j + 1][0] - bflo_f(phi[2]));
                plo[3] = bfpack(s[2 * j + 1][3] - bfhi_f(phi[3]),
                                s[2 * j + 1][2] - bflo_f(phi[3]));
#pragma unroll
                for (int fo = 0; fo < 8; fo++) {
                    int vrow = (8 * fo + g) * KST + kB / 2 + 8 * j;
                    uint2 u0 = Vtt[vrow + tig];
                    uint2 u1 = Vtt[vrow + tig + 4];
                    mma16(o[fo], phi, u0.x, u1.x);
                    mma16(o[fo], plo, u0.x, u1.x);
                    mma16(o[fo], phi, u0.y, u1.y);
                }
            }
        }

        // ---- combine the two key-half groups, write output
        __syncthreads();   // all K/V reads done; safe to overlay K0/V0
        if (nh == 1) {
#pragma unroll
            for (int f = 0; f < 8; f++) {
                int cc = 8 * f + 2 * tig;
                *(float2*)&Osm[rlo * OST + cc] = make_float2(o[f][0], o[f][1]);
                *(float2*)&Osm[rhi * OST + cc] = make_float2(o[f][2], o[f][3]);
            }
            if (tig == 0) {
                msm[rlo] = mA; lsm[rlo] = lA;
                msm[rhi] = mB; lsm[rhi] = lB;
            }
        }
        __syncthreads();
        if (nh == 0) {
            const float m1A = msm[rlo], l1A = lsm[rlo];
            const float m1B = msm[rhi], l1B = lsm[rhi];
            const float MA = fmaxf(mA, m1A), MB = fmaxf(mB, m1B);
            const float w0A = __expf(mA - MA),  w1A = __expf(m1A - MA);
            const float w0B = __expf(mB - MB),  w1B = __expf(m1B - MB);
            const float invA = 1.f / (lA * w0A + l1A * w1A);
            const float invB = 1.f / (lB * w0B + l1B * w1B);
            float* or0 = out + ((size_t)b * T_ + q0 + rlo) * H_;
            float* or1 = out + ((size_t)b * T_ + q0 + rhi) * H_;
#pragma unroll
            for (int f = 0; f < 8; f++) {
                int cc = 8 * f + 2 * tig;
                float2 p0 = *(const float2*)&Osm[rlo * OST + cc];
                float2 p1 = *(const float2*)&Osm[rhi * OST + cc];
                *(float2*)&or0[cc] = make_float2(
                    (o[f][0] * w0A + p0.x * w1A) * invA,
                    (o[f][1] * w0A + p0.y * w1A) * invA);
                *(float2*)&or1[cc] = make_float2(
                    (o[f][2] * w0B + p1.x * w1B) * invB,
                    (o[f][3] * w0B + p1.y * w1B) * invB);
            }
        }
    }
}

// ---------------------------------------------------------------------------

extern "C" void kernel_launch(void* const* d_in, const int* in_sizes, int n_in,
                              void* d_out, int out_size)
{
    const float* x  = (const float*)d_in[0];
    const float* Wk = (const float*)d_in[1];
    const float* Wq = (const float*)d_in[2];
    const float* Wv = (const float*)d_in[3];
    float* out = (float*)d_out;

    prep_w<<<768, 256>>>(Wq, Wk, Wv);

    const int psmem = (2 * 128 * PW + 2 * 192 * PW) * (int)sizeof(float2); // 174080
    cudaFuncSetAttribute(proj_kernel, cudaFuncAttributeMaxDynamicSharedMemorySize, psmem);
    proj_kernel<<<128, 256, psmem>>>(x);

    const int asmem = 4 * 64 * KST * (int)sizeof(uint2); // 73728
    cudaFuncSetAttribute(attn_kernel, cudaFuncAttributeMaxDynamicSharedMemorySize, asmem);
    attn_kernel<<<dim3(32, B_), 256, asmem>>>(out);
}